// round 17
// baseline (speedup 1.0000x reference)
#include <cuda_runtime.h>
#include <cuda_fp16.h>

// GaussianWarpingScheme on GB300 — round 17.
// K1: pure transpose im (B,C,H,W) f32 -> fp16 HWC scratch (LTS floor ~7.5us).
// K2: param kernel: per pixel float4 fused tap weights + packed (xb,y0,y1).
// K3: main, quad layout (xsel,csel): 2 gather LDG.128 per lane; each
//     instruction's per-pixel footprint is the 64B x-pair (~1.25 lines)
//     => gather replay-wavefronts 2.5/px (was 4). SHFL-combine, no smem.

#define Bn 8
#define Cn 16
#define Hn 256
#define Wn 256
#define HWn (Hn * Wn)
#define NPIX (Bn * HWn)

__device__ __half  g_imH[(size_t)NPIX * Cn];   // 32 MB channel-last scratch
__device__ float4  g_wt[NPIX];                 // fused tap weights
__device__ int     g_pk[NPIX];                 // xb | y0<<8 | y1<<16

// ---- packed f32x2 helpers ----
__device__ __forceinline__ unsigned long long f2pack(float lo, float hi) {
    unsigned long long r;
    asm("mov.b64 %0,{%1,%2};" : "=l"(r) : "f"(lo), "f"(hi));
    return r;
}
__device__ __forceinline__ unsigned long long h2f2(unsigned int h2) {
    const float2 f = __half22float2(*(const __half2*)&h2);
    return f2pack(f.x, f.y);
}
__device__ __forceinline__ unsigned long long fma2(unsigned long long a,
                                                   unsigned long long b,
                                                   unsigned long long c) {
    unsigned long long d;
    asm("fma.rn.f32x2 %0,%1,%2,%3;" : "=l"(d) : "l"(a), "l"(b), "l"(c));
    return d;
}
__device__ __forceinline__ unsigned long long mul2(unsigned long long a,
                                                   unsigned long long b) {
    unsigned long long d;
    asm("mul.rn.f32x2 %0,%1,%2;" : "=l"(d) : "l"(a), "l"(b));
    return d;
}
__device__ __forceinline__ unsigned long long add2(unsigned long long a,
                                                   unsigned long long b) {
    unsigned long long d;
    asm("add.rn.f32x2 %0,%1,%2;" : "=l"(d) : "l"(a), "l"(b));
    return d;
}
__device__ __forceinline__ float2 f2unpack(unsigned long long a) {
    float2 f;
    asm("mov.b64 {%0,%1},%2;" : "=f"(f.x), "=f"(f.y) : "l"(a));
    return f;
}

// ---------------- K1: transpose (B,C,H,W) f32 -> (B,H,W,C) fp16 ----------------
__global__ void __launch_bounds__(256)
transpose_chw_hwc(const float* __restrict__ im)
{
    const int bh = blockIdx.x;          // 0 .. B*H-1
    const int b  = bh >> 8;
    const int h  = bh & (Hn - 1);
    const int wv = threadIdx.x;

    const float* src = im + ((size_t)(b * Cn) * Hn + h) * Wn + wv;
    __half* dst = g_imH + ((size_t)((b << 8) + h) * Wn + wv) * Cn;

    __half hv[Cn];
#pragma unroll
    for (int c = 0; c < Cn; c++)
        hv[c] = __float2half_rn(src[(size_t)c * HWn]);

    *(uint4*)(dst)     = *(const uint4*)(hv);
    *(uint4*)(dst + 8) = *(const uint4*)(hv + 8);
}

// ---------------- K2: per-pixel params ----------------
__global__ void __launch_bounds__(256)
param_pass(const float* __restrict__ w)
{
    const int p   = blockIdx.x * 256 + threadIdx.x;
    const int b   = p >> 16;
    const int rem = p & (HWn - 1);
    const int ho  = rem >> 8;
    const int wo  = rem & (Wn - 1);

    const float w0 = w[b * 2 * HWn + rem];
    const float w1 = w[b * 2 * HWn + HWn + rem];

    const float bx = -1.0f + (float)wo * (2.0f / 255.0f);
    const float by = -1.0f + (float)ho * (2.0f / 255.0f);
    const float x = ((bx - w0) + 1.0f) * 0.5f * 255.0f;
    const float y = ((by - w1) + 1.0f) * 0.5f * 255.0f;
    const int ix = (int)floorf(x);
    const int iy = (int)floorf(y);
    const float fx = x - (float)ix;
    const float fy = y - (float)iy;

    const float wx0m = (ix     >= 0 && ix     < Wn) ? __expf(-8.0f * fx * fx)               : 0.0f;
    const float wx1m = (ix + 1 >= 0 && ix + 1 < Wn) ? __expf(-8.0f * (1.0f-fx) * (1.0f-fx)) : 0.0f;
    const float wy0m = (iy     >= 0 && iy     < Hn) ? __expf(-8.0f * fy * fy)               : 0.0f;
    const float wy1m = (iy + 1 >= 0 && iy + 1 < Hn) ? __expf(-8.0f * (1.0f-fy) * (1.0f-fy)) : 0.0f;

    // x-pair base with boundary-correct slot weights
    const int xb = min(max(ix, 0), Wn - 2);
    float pw0 = 0.0f, pw1 = 0.0f;
    if (ix     == xb)     pw0 += wx0m;
    if (ix + 1 == xb)     pw0 += wx1m;            // ix = -1
    if (ix     == xb + 1) pw1 += wx0m;            // ix = 255
    if (ix + 1 == xb + 1) pw1 += wx1m;

    const int y0 = min(max(iy,     0), Hn - 1);
    const int y1 = min(max(iy + 1, 0), Hn - 1);

    g_wt[p] = make_float4(pw0 * wy0m, pw1 * wy0m, pw0 * wy1m, pw1 * wy1m);
    g_pk[p] = xb | (y0 << 8) | (y1 << 16);
}

// ---------------- K3: quad-gather main ----------------
__global__ void __launch_bounds__(256)
gauss_warp_main(float* __restrict__ out)
{
    const unsigned FULL = 0xffffffffu;
    const int tid  = threadIdx.x;
    const int xsel = tid & 1;                     // x tap of the pair
    const int csel = (tid >> 1) & 1;              // channel half

    const int p   = blockIdx.x * 64 + (tid >> 2); // one pixel per lane-quad
    const int b   = p >> 16;
    const int rem = p & (HWn - 1);

    // ---- precomputed params (quad-broadcast, coalesced) ----
    const float4 wt = __ldg(&g_wt[p]);
    const int    pk = __ldg(&g_pk[p]);
    const int xb =  pk        & 0xff;
    const int y0 = (pk >> 8)  & 0xff;
    const int y1 = (pk >> 16) & 0xff;

    const float wa = xsel ? wt.y : wt.x;          // this x tap, row y0
    const float wb = xsel ? wt.w : wt.z;          // this x tap, row y1
    const unsigned long long W0 = f2pack(wa, wa);
    const unsigned long long W1 = f2pack(wb, wb);

    // ---- gathers: 2x LDG.128; quad covers the 64B x-pair per row ----
    const __half* bh = g_imH + (size_t)b * HWn * Cn;
    const size_t lo  = (size_t)(xb + xsel) * Cn + csel * 8;

    const uint4 r0 = __ldg((const uint4*)(bh + ((size_t)(y0 << 8) * Cn) + lo));
    const uint4 r1 = __ldg((const uint4*)(bh + ((size_t)(y1 << 8) * Cn) + lo));

    // ---- accumulate own x-tap (8 channels = 4 f32x2) ----
    unsigned long long s0 = mul2(W0, h2f2(r0.x));
    unsigned long long s1 = mul2(W0, h2f2(r0.y));
    unsigned long long s2 = mul2(W0, h2f2(r0.z));
    unsigned long long s3 = mul2(W0, h2f2(r0.w));
    s0 = fma2(W1, h2f2(r1.x), s0);
    s1 = fma2(W1, h2f2(r1.y), s1);
    s2 = fma2(W1, h2f2(r1.z), s2);
    s3 = fma2(W1, h2f2(r1.w), s3);

    // ---- cross-x combine via butterfly shuffle (partner = lane^1) ----
    s0 = add2(s0, __shfl_xor_sync(FULL, s0, 1));
    s1 = add2(s1, __shfl_xor_sync(FULL, s1, 1));
    s2 = add2(s2, __shfl_xor_sync(FULL, s2, 1));
    s3 = add2(s3, __shfl_xor_sync(FULL, s3, 1));

    // ---- stores: lane pair splits the 8 channels (4 each) ----
    const float2 fa = f2unpack(xsel ? s2 : s0);
    const float2 fb = f2unpack(xsel ? s3 : s1);

    float* op = out + (size_t)b * Cn * HWn
                    + (size_t)(csel * 8 + xsel * 4) * HWn + rem;
    op[0 * HWn] = fa.x;
    op[1 * HWn] = fa.y;
    op[2 * HWn] = fb.x;
    op[3 * HWn] = fb.y;
}

extern "C" void kernel_launch(void* const* d_in, const int* in_sizes, int n_in,
                              void* d_out, int out_size)
{
    const float* im = (const float*)d_in[0];
    const float* w  = (const float*)d_in[1];
    if (n_in >= 2 && in_sizes[0] == Bn * 2 * HWn && in_sizes[1] == Bn * Cn * HWn) {
        im = (const float*)d_in[1];
        w  = (const float*)d_in[0];
    }
    float* out = (float*)d_out;

    param_pass<<<NPIX / 256, 256>>>(w);          // small, independent of scratch
    transpose_chw_hwc<<<Bn * Hn, 256>>>(im);
    gauss_warp_main<<<NPIX / 64, 256>>>(out);
}